// round 3
// baseline (speedup 1.0000x reference)
#include <cuda_runtime.h>
#include <cuda_bf16.h>

#define FIVE_K 6
#define OUT_N  512
#define IN_N   1024
#define HID_N  32
#define B_N    256

typedef unsigned long long ull;

// ---------------------------------------------------------------------------
// f32x2 packed helpers (FFMA2 — ptxas never emits these from C++)
// ---------------------------------------------------------------------------
__device__ __forceinline__ ull pack2(float a, float b) {
    ull r;
    asm("mov.b64 %0, {%1, %2};"
        : "=l"(r) : "r"(__float_as_uint(a)), "r"(__float_as_uint(b)));
    return r;
}
__device__ __forceinline__ ull pdup(float a) {
    ull r;
    asm("mov.b64 %0, {%1, %1};" : "=l"(r) : "r"(__float_as_uint(a)));
    return r;
}
__device__ __forceinline__ void fma2(ull& d, ull a, ull b) {
    asm("fma.rn.f32x2 %0, %1, %2, %0;" : "+l"(d) : "l"(a), "l"(b));
}
__device__ __forceinline__ void unpack2(ull v, float& lo, float& hi) {
    unsigned ulo, uhi;
    asm("mov.b64 {%0, %1}, %2;" : "=r"(ulo), "=r"(uhi) : "l"(v));
    lo = __uint_as_float(ulo);
    hi = __uint_as_float(uhi);
}

// 64-bit topk key: (orderable_float << 10) | (1023 - idx)
// max key == argmax with ties broken toward the smaller index.
__device__ __forceinline__ ull mk_key(float x, int gi) {
    unsigned u = __float_as_uint(x);
    unsigned ord = (u & 0x80000000u) ? ~u : (u | 0x80000000u);
    return ((ull)ord << 10) | (ull)(1023 - gi);
}

// ---------------------------------------------------------------------------
// Single fused kernel: one block (256 threads) per output unit o.
//   warp 0   : top-6 of mask row o (register tree + 64-bit butterfly)
//   warps 1-3: stage W2 / W3 / W4 into smem      } overlapped
//   then     : W1 rows for the 6 picked features + per-thread input gather
//   then     : 4-layer MLP, all FMA work as packed f32x2 (FFMA2)
// ---------------------------------------------------------------------------
__global__ __launch_bounds__(B_N, 2)
void blayer_fused(const float* __restrict__ inputs,
                  const float* __restrict__ mask,
                  const float* __restrict__ W1,
                  const float* __restrict__ W2,
                  const float* __restrict__ W3,
                  const float* __restrict__ W4,
                  float* __restrict__ out)
{
    __shared__ float sW1[FIVE_K * HID_N];   // 768 B
    __shared__ float sW2[HID_N * HID_N];    // 4 KB
    __shared__ float sW3[HID_N * HID_N];    // 4 KB
    __shared__ float sW4[HID_N];
    __shared__ int   sIdx[FIVE_K];

    const int o    = blockIdx.x;
    const int tid  = threadIdx.x;
    const int warp = tid >> 5;
    const int lane = tid & 31;

    // ---------------- phase 1: topk (warp 0) || weight staging (warps 1-3)
    if (warp == 0) {
        const float4* rf4 = reinterpret_cast<const float4*>(mask + o * IN_N);
        ull k[32];
#pragma unroll
        for (int c = 0; c < 8; c++) {
            float4 v = rf4[c * 32 + lane];
            int gb = 4 * (c * 32 + lane);
            k[c * 4 + 0] = mk_key(v.x, gb + 0);
            k[c * 4 + 1] = mk_key(v.y, gb + 1);
            k[c * 4 + 2] = mk_key(v.z, gb + 2);
            k[c * 4 + 3] = mk_key(v.w, gb + 3);
        }
#pragma unroll
        for (int it = 0; it < FIVE_K; it++) {
            ull t[16];
#pragma unroll
            for (int i = 0; i < 16; i++) t[i] = (k[i] > k[i + 16]) ? k[i] : k[i + 16];
#pragma unroll
            for (int i = 0; i < 8; i++)  t[i] = (t[i] > t[i + 8]) ? t[i] : t[i + 8];
#pragma unroll
            for (int i = 0; i < 4; i++)  t[i] = (t[i] > t[i + 4]) ? t[i] : t[i + 4];
            t[0] = (t[0] > t[2]) ? t[0] : t[2];
            t[1] = (t[1] > t[3]) ? t[1] : t[3];
            ull best = (t[0] > t[1]) ? t[0] : t[1];
#pragma unroll
            for (int off = 16; off >= 1; off >>= 1) {
                ull ob = __shfl_xor_sync(0xFFFFFFFFu, best, off);
                if (ob > best) best = ob;
            }
            if (lane == 0)
                sIdx[it] = 1023 - (int)(best & 1023ull);
#pragma unroll
            for (int c = 0; c < 32; c++)
                if (k[c] == best) k[c] = 0ull;
        }
    } else if (warp == 1) {
        const float4* g = reinterpret_cast<const float4*>(W2 + o * HID_N * HID_N);
        float4* s = reinterpret_cast<float4*>(sW2);
#pragma unroll
        for (int q = 0; q < 8; q++) s[q * 32 + lane] = g[q * 32 + lane];
    } else if (warp == 2) {
        const float4* g = reinterpret_cast<const float4*>(W3 + o * HID_N * HID_N);
        float4* s = reinterpret_cast<float4*>(sW3);
#pragma unroll
        for (int q = 0; q < 8; q++) s[q * 32 + lane] = g[q * 32 + lane];
    } else if (warp == 3) {
        if (lane < 8)
            reinterpret_cast<float4*>(sW4)[lane] =
                reinterpret_cast<const float4*>(W4 + o * HID_N)[lane];
    }
    __syncthreads();   // sIdx + sW2/sW3/sW4 ready

    // ---------------- phase 2: W1 rows + per-thread input gather
    if (tid < FIVE_K * HID_N) {
        int j = tid >> 5, h = tid & 31;
        sW1[tid] = W1[(o * IN_N + sIdx[j]) * HID_N + h];
    }
    float x[FIVE_K];
#pragma unroll
    for (int j = 0; j < FIVE_K; j++)
        x[j] = inputs[tid * IN_N + sIdx[j]];     // L2-resident gather
    __syncthreads();   // sW1 ready

    // ---------------- phase 3: MLP (packed f32x2)
    ull  acc[16];
    float h[HID_N];

    // layer 1: 6 -> 32
#pragma unroll
    for (int q = 0; q < 16; q++) acc[q] = 0ull;
#pragma unroll
    for (int j = 0; j < FIVE_K; j++) {
        ull a2 = pdup(x[j]);
        const ulonglong2* wr = reinterpret_cast<const ulonglong2*>(sW1 + j * HID_N);
#pragma unroll
        for (int q = 0; q < 8; q++) {
            ulonglong2 w = wr[q];
            fma2(acc[2 * q],     a2, w.x);
            fma2(acc[2 * q + 1], a2, w.y);
        }
    }
#pragma unroll
    for (int q = 0; q < 16; q++) {
        float lo, hi; unpack2(acc[q], lo, hi);
        h[2 * q]     = fmaxf(lo, 0.f);
        h[2 * q + 1] = fmaxf(hi, 0.f);
    }

    // layer 2: 32 -> 32
#pragma unroll
    for (int q = 0; q < 16; q++) acc[q] = 0ull;
#pragma unroll
    for (int hh = 0; hh < HID_N; hh++) {
        ull a2 = pdup(h[hh]);
        const ulonglong2* wr = reinterpret_cast<const ulonglong2*>(sW2 + hh * HID_N);
#pragma unroll
        for (int q = 0; q < 8; q++) {
            ulonglong2 w = wr[q];
            fma2(acc[2 * q],     a2, w.x);
            fma2(acc[2 * q + 1], a2, w.y);
        }
    }
#pragma unroll
    for (int q = 0; q < 16; q++) {
        float lo, hi; unpack2(acc[q], lo, hi);
        h[2 * q]     = fmaxf(lo, 0.f);
        h[2 * q + 1] = fmaxf(hi, 0.f);
    }

    // layer 3: 32 -> 32
#pragma unroll
    for (int q = 0; q < 16; q++) acc[q] = 0ull;
#pragma unroll
    for (int hh = 0; hh < HID_N; hh++) {
        ull a2 = pdup(h[hh]);
        const ulonglong2* wr = reinterpret_cast<const ulonglong2*>(sW3 + hh * HID_N);
#pragma unroll
        for (int q = 0; q < 8; q++) {
            ulonglong2 w = wr[q];
            fma2(acc[2 * q],     a2, w.x);
            fma2(acc[2 * q + 1], a2, w.y);
        }
    }
#pragma unroll
    for (int q = 0; q < 16; q++) {
        float lo, hi; unpack2(acc[q], lo, hi);
        h[2 * q]     = fmaxf(lo, 0.f);
        h[2 * q + 1] = fmaxf(hi, 0.f);
    }

    // layer 4: 32 -> 1, sign (sigmoid(z) >= 0.5 <=> z >= 0)
    ull accA = 0ull, accB = 0ull;
    const ulonglong2* w4 = reinterpret_cast<const ulonglong2*>(sW4);
#pragma unroll
    for (int p = 0; p < 8; p++) {
        ulonglong2 w = w4[p];
        fma2(accA, pack2(h[4 * p],     h[4 * p + 1]), w.x);
        fma2(accB, pack2(h[4 * p + 2], h[4 * p + 3]), w.y);
    }
    float a0, a1, b0, b1;
    unpack2(accA, a0, a1);
    unpack2(accB, b0, b1);
    float z = (a0 + a1) + (b0 + b1);

    out[tid * OUT_N + o] = (z >= 0.f) ? 1.f : -1.f;
}

// ---------------------------------------------------------------------------
extern "C" void kernel_launch(void* const* d_in, const int* in_sizes, int n_in,
                              void* d_out, int out_size)
{
    const float* inputs = (const float*)d_in[0];  // (B, IN)
    const float* mask   = (const float*)d_in[1];  // (OUT, IN)
    const float* W1     = (const float*)d_in[2];  // (OUT, IN, HID)
    const float* W2     = (const float*)d_in[3];  // (OUT, HID, HID)
    const float* W3     = (const float*)d_in[4];  // (OUT, HID, HID)
    const float* W4     = (const float*)d_in[5];  // (OUT, HID, 1)
    float* out = (float*)d_out;                   // (B, OUT)

    blayer_fused<<<OUT_N, B_N>>>(inputs, mask, W1, W2, W3, W4, out);
}

// round 4
// speedup vs baseline: 1.2074x; 1.2074x over previous
#include <cuda_runtime.h>
#include <cuda_bf16.h>

#define FIVE_K 6
#define OUT_N  512
#define IN_N   1024
#define HID_N  32
#define B_N    256

typedef unsigned long long ull;

// ---------------------------------------------------------------------------
// f32x2 packed helpers (FFMA2 — ptxas never emits these from C++)
// ---------------------------------------------------------------------------
__device__ __forceinline__ ull pack2(float a, float b) {
    ull r;
    asm("mov.b64 %0, {%1, %2};"
        : "=l"(r) : "r"(__float_as_uint(a)), "r"(__float_as_uint(b)));
    return r;
}
__device__ __forceinline__ ull pdup(float a) {
    ull r;
    asm("mov.b64 %0, {%1, %1};" : "=l"(r) : "r"(__float_as_uint(a)));
    return r;
}
__device__ __forceinline__ void fma2(ull& d, ull a, ull b) {
    asm("fma.rn.f32x2 %0, %1, %2, %0;" : "+l"(d) : "l"(a), "l"(b));
}
__device__ __forceinline__ void unpack2(ull v, float& lo, float& hi) {
    unsigned ulo, uhi;
    asm("mov.b64 {%0, %1}, %2;" : "=r"(ulo), "=r"(uhi) : "l"(v));
    lo = __uint_as_float(ulo);
    hi = __uint_as_float(uhi);
}

// ---------------------------------------------------------------------------
// topk machinery: 64-bit keys (orderable_float << 10) | (1023 - idx)
// max key == argmax, ties toward smaller index. Pad key = 0 (< any real key).
// ---------------------------------------------------------------------------
__device__ __forceinline__ ull mk_key(float x, int gi) {
    unsigned u = __float_as_uint(x);
    unsigned ord = (u & 0x80000000u) ? ~u : (u | 0x80000000u);
    return ((ull)ord << 10) | (ull)(1023 - gi);
}
__device__ __forceinline__ void cas(ull& a, ull& b) {   // desc: a=max, b=min
    ull hi = a > b ? a : b;
    ull lo = a > b ? b : a;
    a = hi; b = lo;
}
__device__ __forceinline__ ull mx(ull a, ull b) { return a > b ? a : b; }

// sort 6 desc — derived from Batcher odd-even mergesort-8 with 2 -inf pads
__device__ __forceinline__ void sort6(ull* t) {
    cas(t[0], t[1]); cas(t[2], t[3]); cas(t[4], t[5]);
    cas(t[0], t[2]); cas(t[1], t[3]);
    cas(t[1], t[2]);
    cas(t[0], t[4]); cas(t[1], t[5]);
    cas(t[2], t[4]); cas(t[3], t[5]);
    cas(t[1], t[2]); cas(t[3], t[4]);
}
// a, b sorted desc (len 6); a <- sorted top-6 of the union
// (top-k selection trick: t_i = max(a_i, b_{k-1-i}) is the top-k multiset)
__device__ __forceinline__ void merge6(ull* a, const ull* b) {
    ull t[6];
    t[0] = mx(a[0], b[5]); t[1] = mx(a[1], b[4]); t[2] = mx(a[2], b[3]);
    t[3] = mx(a[3], b[2]); t[4] = mx(a[4], b[1]); t[5] = mx(a[5], b[0]);
    sort6(t);
#pragma unroll
    for (int q = 0; q < 6; q++) a[q] = t[q];
}
__device__ __forceinline__ void sort4(ull& a0, ull& a1, ull& a2, ull& a3) {
    cas(a0, a1); cas(a2, a3); cas(a0, a2); cas(a1, a3); cas(a1, a2);
}

// ---------------------------------------------------------------------------
// dense 32->32 layer, 2 batch elems, packed f32x2, in-place activations
// ---------------------------------------------------------------------------
#define DENSE32(SW)                                                          \
    do {                                                                     \
        ull accA[16], accB[16];                                              \
        _Pragma("unroll")                                                    \
        for (int q = 0; q < 16; q++) { accA[q] = 0ull; accB[q] = 0ull; }     \
        _Pragma("unroll")                                                    \
        for (int r = 0; r < 32; r++) {                                       \
            const ulonglong2* wr =                                           \
                reinterpret_cast<const ulonglong2*>((SW) + r * HID_N);       \
            ull dA = pdup(hA[r]), dB = pdup(hB[r]);                          \
            _Pragma("unroll")                                                \
            for (int q = 0; q < 4; q++) {                                    \
                ulonglong2 w = wr[q];                                        \
                fma2(accA[2 * q],     dA, w.x);                              \
                fma2(accA[2 * q + 1], dA, w.y);                              \
                fma2(accB[2 * q],     dB, w.x);                              \
                fma2(accB[2 * q + 1], dB, w.y);                              \
            }                                                                \
            _Pragma("unroll")                                                \
            for (int q = 4; q < 8; q++) {                                    \
                ulonglong2 w = wr[q];                                        \
                fma2(accA[2 * q],     dA, w.x);                              \
                fma2(accA[2 * q + 1], dA, w.y);                              \
                fma2(accB[2 * q],     dB, w.x);                              \
                fma2(accB[2 * q + 1], dB, w.y);                              \
            }                                                                \
        }                                                                    \
        _Pragma("unroll")                                                    \
        for (int q = 0; q < 16; q++) {                                       \
            float lo, hi;                                                    \
            unpack2(accA[q], lo, hi);                                        \
            hA[2 * q] = fmaxf(lo, 0.f); hA[2 * q + 1] = fmaxf(hi, 0.f);      \
            unpack2(accB[q], lo, hi);                                        \
            hB[2 * q] = fmaxf(lo, 0.f); hB[2 * q + 1] = fmaxf(hi, 0.f);      \
        }                                                                    \
    } while (0)

// ---------------------------------------------------------------------------
// Fused kernel: one block (128 threads) per output unit o.
// Thread t handles batch elements t and t+128.
// ---------------------------------------------------------------------------
__global__ __launch_bounds__(128, 3)
void blayer_fused(const float* __restrict__ inputs,
                  const float* __restrict__ mask,
                  const float* __restrict__ W1,
                  const float* __restrict__ W2,
                  const float* __restrict__ W3,
                  const float* __restrict__ W4,
                  float* __restrict__ out)
{
    __shared__ float sW1[FIVE_K * HID_N];
    __shared__ float sW2[HID_N * HID_N];
    __shared__ float sW3[HID_N * HID_N];
    __shared__ float sW4[HID_N];
    __shared__ ull   sLists[4][6];
    __shared__ int   sIdx[FIVE_K];

    const int o    = blockIdx.x;
    const int tid  = threadIdx.x;
    const int warp = tid >> 5;
    const int lane = tid & 31;

    // -- prefetch dense weights into registers (latency hides under topk) --
    const float4* w2g = reinterpret_cast<const float4*>(W2 + o * HID_N * HID_N);
    const float4* w3g = reinterpret_cast<const float4*>(W3 + o * HID_N * HID_N);
    float4 r2a = w2g[tid], r2b = w2g[tid + 128];
    float4 r3a = w3g[tid], r3b = w3g[tid + 128];
    float  w4r = (tid < HID_N) ? W4[o * HID_N + tid] : 0.f;

    // -- cooperative top-6: 8 mask values per thread --
    const float4* mk4 = reinterpret_cast<const float4*>(mask + o * IN_N);
    float4 m0 = mk4[tid], m1 = mk4[tid + 128];

    ull a[6], b[6];
    {
        ull k0 = mk_key(m0.x, 4 * tid + 0);
        ull k1 = mk_key(m0.y, 4 * tid + 1);
        ull k2 = mk_key(m0.z, 4 * tid + 2);
        ull k3 = mk_key(m0.w, 4 * tid + 3);
        ull k4 = mk_key(m1.x, 4 * (tid + 128) + 0);
        ull k5 = mk_key(m1.y, 4 * (tid + 128) + 1);
        ull k6 = mk_key(m1.z, 4 * (tid + 128) + 2);
        ull k7 = mk_key(m1.w, 4 * (tid + 128) + 3);
        sort4(k0, k1, k2, k3);
        sort4(k4, k5, k6, k7);
        a[0] = k0; a[1] = k1; a[2] = k2; a[3] = k3; a[4] = 0; a[5] = 0;
        b[0] = k4; b[1] = k5; b[2] = k6; b[3] = k7; b[4] = 0; b[5] = 0;
        merge6(a, b);
    }
    // warp butterfly: merge sorted-6 lists (all lanes converge)
#pragma unroll
    for (int off = 16; off >= 1; off >>= 1) {
#pragma unroll
        for (int j = 0; j < 6; j++)
            b[j] = __shfl_xor_sync(0xFFFFFFFFu, a[j], off);
        merge6(a, b);
    }
    if (lane == 0) {
#pragma unroll
        for (int j = 0; j < 6; j++) sLists[warp][j] = a[j];
    }

    // -- stage dense weights to smem (overlaps with list publication) --
    reinterpret_cast<float4*>(sW2)[tid]       = r2a;
    reinterpret_cast<float4*>(sW2)[tid + 128] = r2b;
    reinterpret_cast<float4*>(sW3)[tid]       = r3a;
    reinterpret_cast<float4*>(sW3)[tid + 128] = r3b;
    if (tid < HID_N) sW4[tid] = w4r;
    __syncthreads();

    // -- warp 0 merges the 4 warp lists (its own is still in registers) --
    if (warp == 0) {
#pragma unroll
        for (int w = 1; w < 4; w++) {
#pragma unroll
            for (int j = 0; j < 6; j++) b[j] = sLists[w][j];
            merge6(a, b);
        }
        if (lane == 0) {
#pragma unroll
            for (int j = 0; j < 6; j++)
                sIdx[j] = 1023 - (int)(a[j] & 1023ull);
        }
    }
    __syncthreads();

    // -- gather W1 rows + the 6 input values for my two batch elements --
    int idx[FIVE_K];
#pragma unroll
    for (int j = 0; j < FIVE_K; j++) idx[j] = sIdx[j];

#pragma unroll
    for (int t = tid; t < FIVE_K * HID_N; t += 128) {
        int j = t >> 5, k = t & 31;
        sW1[t] = W1[(o * IN_N + sIdx[j]) * HID_N + k];
    }
    float xA[FIVE_K], xB[FIVE_K];
#pragma unroll
    for (int j = 0; j < FIVE_K; j++) {
        xA[j] = inputs[tid * IN_N + idx[j]];
        xB[j] = inputs[(tid + 128) * IN_N + idx[j]];
    }
    __syncthreads();

    // ---- layer 1: 6 -> 32 ----
    float hA[HID_N], hB[HID_N];
    {
        ull accA[16], accB[16];
#pragma unroll
        for (int q = 0; q < 16; q++) { accA[q] = 0ull; accB[q] = 0ull; }
#pragma unroll
        for (int r = 0; r < FIVE_K; r++) {
            const ulonglong2* wr =
                reinterpret_cast<const ulonglong2*>(sW1 + r * HID_N);
            ull dA = pdup(xA[r]), dB = pdup(xB[r]);
#pragma unroll
            for (int q = 0; q < 8; q++) {
                ulonglong2 w = wr[q];
                fma2(accA[2 * q],     dA, w.x);
                fma2(accA[2 * q + 1], dA, w.y);
                fma2(accB[2 * q],     dB, w.x);
                fma2(accB[2 * q + 1], dB, w.y);
            }
        }
#pragma unroll
        for (int q = 0; q < 16; q++) {
            float lo, hi;
            unpack2(accA[q], lo, hi);
            hA[2 * q] = fmaxf(lo, 0.f); hA[2 * q + 1] = fmaxf(hi, 0.f);
            unpack2(accB[q], lo, hi);
            hB[2 * q] = fmaxf(lo, 0.f); hB[2 * q + 1] = fmaxf(hi, 0.f);
        }
    }

    // ---- layers 2 & 3: 32 -> 32 (in-place) ----
    DENSE32(sW2);
    DENSE32(sW3);

    // ---- layer 4: 32 -> 1, sign (sigmoid(z) >= 0.5 <=> z >= 0) ----
    ull sA = 0ull, sB = 0ull;
    const ull* w4p = reinterpret_cast<const ull*>(sW4);
#pragma unroll
    for (int p = 0; p < 16; p++) {
        ull w = w4p[p];
        fma2(sA, pack2(hA[2 * p], hA[2 * p + 1]), w);
        fma2(sB, pack2(hB[2 * p], hB[2 * p + 1]), w);
    }
    float l0, l1;
    unpack2(sA, l0, l1);
    float zA = l0 + l1;
    unpack2(sB, l0, l1);
    float zB = l0 + l1;

    out[tid * OUT_N + o]         = (zA >= 0.f) ? 1.f : -1.f;
    out[(tid + 128) * OUT_N + o] = (zB >= 0.f) ? 1.f : -1.f;
}

// ---------------------------------------------------------------------------
extern "C" void kernel_launch(void* const* d_in, const int* in_sizes, int n_in,
                              void* d_out, int out_size)
{
    const float* inputs = (const float*)d_in[0];  // (B, IN)
    const float* mask   = (const float*)d_in[1];  // (OUT, IN)
    const float* W1     = (const float*)d_in[2];  // (OUT, IN, HID)
    const float* W2     = (const float*)d_in[3];  // (OUT, HID, HID)
    const float* W3     = (const float*)d_in[4];  // (OUT, HID, HID)
    const float* W4     = (const float*)d_in[5];  // (OUT, HID, 1)
    float* out = (float*)d_out;                   // (B, OUT)

    blayer_fused<<<OUT_N, 128>>>(inputs, mask, W1, W2, W3, W4, out);
}